// round 8
// baseline (speedup 1.0000x reference)
#include <cuda_runtime.h>
#include <cuda_bf16.h>
#include <cstdint>

#define M_TOK 16384   // B*S tokens
#define K_DIM 2048    // DIN
#define N_DIM 2048    // DOUT

// ---------------------------------------------------------------------------
// Scratch (__device__ globals; no allocations allowed)
// ---------------------------------------------------------------------------
__device__ int8_t g_xq[(size_t)M_TOK * K_DIM];      // 32 MB quantized activations
__device__ float  g_xscale[M_TOK];                  // per-token scale
__device__ int8_t g_w[(size_t)N_DIM * K_DIM];       // 4 MB ternary weights as int8
__device__ int    g_acc[(size_t)M_TOK * N_DIM];     // 128 MB int32 GEMM output

// ---------------------------------------------------------------------------
// Kernel 0: repack ternary int32 weights -> int8
// ---------------------------------------------------------------------------
__global__ void pack_w_kernel(const int* __restrict__ wt) {
    int idx = blockIdx.x * blockDim.x + threadIdx.x;    // group of 4 elements
    if (idx >= (N_DIM * K_DIM) / 4) return;
    int4 v = __ldcs(&((const int4*)wt)[idx]);
    char4 c;
    c.x = (char)v.x; c.y = (char)v.y; c.z = (char)v.z; c.w = (char)v.w;
    ((char4*)g_w)[idx] = c;
}

// ---------------------------------------------------------------------------
// Block reductions (256 threads)
// ---------------------------------------------------------------------------
__device__ __forceinline__ float2 block_reduce_sum2(float a, float b, float* sh) {
    #pragma unroll
    for (int o = 16; o > 0; o >>= 1) {
        a += __shfl_xor_sync(0xFFFFFFFFu, a, o);
        b += __shfl_xor_sync(0xFFFFFFFFu, b, o);
    }
    int w = threadIdx.x >> 5, l = threadIdx.x & 31;
    if (l == 0) { sh[w] = a; sh[w + 8] = b; }
    __syncthreads();
    if (threadIdx.x < 32) {
        float va = (l < 8) ? sh[l] : 0.f;
        float vb = (l < 8) ? sh[l + 8] : 0.f;
        #pragma unroll
        for (int o = 4; o > 0; o >>= 1) {
            va += __shfl_xor_sync(0xFFFFFFFFu, va, o);
            vb += __shfl_xor_sync(0xFFFFFFFFu, vb, o);
        }
        if (l == 0) { sh[16] = va; sh[17] = vb; }
    }
    __syncthreads();
    float2 r = make_float2(sh[16], sh[17]);
    __syncthreads();
    return r;
}

__device__ __forceinline__ float block_reduce_max(float v, float* sh) {
    #pragma unroll
    for (int o = 16; o > 0; o >>= 1)
        v = fmaxf(v, __shfl_xor_sync(0xFFFFFFFFu, v, o));
    int w = threadIdx.x >> 5, l = threadIdx.x & 31;
    if (l == 0) sh[w] = v;
    __syncthreads();
    if (threadIdx.x < 32) {
        float m = (l < 8) ? sh[l] : -1e30f;
        #pragma unroll
        for (int o = 4; o > 0; o >>= 1)
            m = fmaxf(m, __shfl_xor_sync(0xFFFFFFFFu, m, o));
        if (l == 0) sh[16] = m;
    }
    __syncthreads();
    float r = sh[16];
    __syncthreads();
    return r;
}

// ---------------------------------------------------------------------------
// Kernel 1: fused input LayerNorm + per-token int8 absmax quantization.
// ---------------------------------------------------------------------------
__global__ __launch_bounds__(256) void ln_quant_kernel(const float* __restrict__ x) {
    __shared__ float sh[18];
    const int row = blockIdx.x;
    const int t = threadIdx.x;
    const float4* xr = (const float4*)(x + (size_t)row * K_DIM);

    float v[8];
    float4 a = __ldcs(&xr[t]);
    float4 b = __ldcs(&xr[t + 256]);
    v[0]=a.x; v[1]=a.y; v[2]=a.z; v[3]=a.w;
    v[4]=b.x; v[5]=b.y; v[6]=b.z; v[7]=b.w;

    float s = 0.f, ss = 0.f;
    #pragma unroll
    for (int i = 0; i < 8; i++) { s += v[i]; ss += v[i]*v[i]; }
    float2 tot = block_reduce_sum2(s, ss, sh);

    const float invn = 1.0f / (float)K_DIM;
    float mu  = tot.x * invn;
    float var = fmaxf(tot.y * invn - mu * mu, 0.f);   // biased variance (torch default)
    float rstd = rsqrtf(var + 1e-5f);

    float amax = 0.f;
    #pragma unroll
    for (int i = 0; i < 8; i++) {
        v[i] = (v[i] - mu) * rstd;
        amax = fmaxf(amax, fabsf(v[i]));
    }
    amax = block_reduce_max(amax, sh);
    amax = fmaxf(amax, 1e-5f);
    float scale = amax * (1.0f / 127.0f);
    float inv   = 127.0f / amax;

    char q[8];
    #pragma unroll
    for (int i = 0; i < 8; i++) {
        int qi = (int)rintf(v[i] * inv);       // round-half-even, matches jnp.round
        qi = max(-127, min(127, qi));
        q[i] = (char)qi;
    }
    char4* dst = (char4*)(g_xq + (size_t)row * K_DIM);
    char4 c0; c0.x=q[0]; c0.y=q[1]; c0.z=q[2]; c0.w=q[3];
    char4 c1; c1.x=q[4]; c1.y=q[5]; c1.z=q[6]; c1.w=q[7];
    dst[t] = c0;
    dst[t + 256] = c1;
    if (t == 0) g_xscale[row] = scale;
}

// ---------------------------------------------------------------------------
// Kernel 2: int8 tensor-core GEMM via mma.sync.m16n8k32.
// CTA tile 128x256, K staged 128B, 8 warps (2x4), warp tile 64x64,
// 4-stage cp.async pipeline + register-level fragment double-buffering.
// acc[m][n] = sum_k xq[m][k] * w[n][k]
// ---------------------------------------------------------------------------
#define BM  128
#define BN  256
#define BKB 128   // K-bytes per stage
#define NIT (K_DIM / BKB)   // 16
#define NSTAGE 4
#define A_BYTES (BM * BKB)                // 16 KB
#define B_BYTES (BN * BKB)                // 32 KB
#define STAGE_BYTES (A_BYTES + B_BYTES)   // 48 KB
#define SMEM_DYN (NSTAGE * STAGE_BYTES)   // 192 KB

__device__ __forceinline__ uint32_t smem_u32(const void* p) {
    uint32_t a;
    asm("{ .reg .u64 t; cvta.to.shared.u64 t, %1; cvt.u32.u64 %0, t; }" : "=r"(a) : "l"(p));
    return a;
}

// swizzled byte offset within a [rows x 128B] tile
__device__ __forceinline__ uint32_t swz(int row, int c) {
    return (uint32_t)(row * 128 + ((c ^ (row & 7)) << 4));
}

__device__ __forceinline__ void cp16(uint32_t saddr, const void* g) {
    asm volatile("cp.async.cg.shared.global [%0], [%1], 16;" :: "r"(saddr), "l"(g));
}

__device__ __forceinline__ void ldsm4(uint32_t* r, uint32_t addr) {
    asm volatile("ldmatrix.sync.aligned.m8n8.x4.shared.b16 {%0,%1,%2,%3}, [%4];"
                 : "=r"(r[0]), "=r"(r[1]), "=r"(r[2]), "=r"(r[3]) : "r"(addr));
}

__device__ __forceinline__ void mma_s8(int* c, const uint32_t* a, const uint32_t* b) {
    asm volatile(
        "mma.sync.aligned.m16n8k32.row.col.s32.s8.s8.s32 "
        "{%0,%1,%2,%3}, {%4,%5,%6,%7}, {%8,%9}, {%0,%1,%2,%3};"
        : "+r"(c[0]), "+r"(c[1]), "+r"(c[2]), "+r"(c[3])
        : "r"(a[0]), "r"(a[1]), "r"(a[2]), "r"(a[3]), "r"(b[0]), "r"(b[1]));
}

__global__ __launch_bounds__(256, 1) void gemm_kernel(int m0) {
    extern __shared__ uint8_t smem[];

    const int tid  = threadIdx.x;
    const int wid  = tid >> 5;
    const int lane = tid & 31;
    const int wm   = wid >> 2;          // 0..1 -> m offset wm*64
    const int wn   = wid & 3;           // 0..3 -> n offset wn*64
    const int bm   = m0 + (int)blockIdx.y * BM;
    const int bn   = (int)blockIdx.x * BN;
    const uint32_t sbase = smem_u32(smem);

    int acc[4][8][4];
    #pragma unroll
    for (int i = 0; i < 4; i++)
        #pragma unroll
        for (int j = 0; j < 8; j++)
            #pragma unroll
            for (int r = 0; r < 4; r++) acc[i][j][r] = 0;

    // cooperative load of one stage: A 1024 + B 2048 chunks of 16B = 12/thread
    auto load_stage = [&](int st, int k0) {
        uint32_t sa = sbase + st * STAGE_BYTES;
        uint32_t sb = sa + A_BYTES;
        #pragma unroll
        for (int i = 0; i < 12; i++) {
            int idx = tid + i * 256;        // 0..3071
            if (idx < 1024) {
                int row = idx >> 3, c = idx & 7;
                cp16(sa + swz(row, c), g_xq + (size_t)(bm + row) * K_DIM + k0 + c * 16);
            } else {
                int j = idx - 1024;
                int row = j >> 3, c = j & 7;
                cp16(sb + swz(row, c), g_w + (size_t)(bn + row) * K_DIM + k0 + c * 16);
            }
        }
    };

    // prologue: 3 stages in flight
    load_stage(0, 0);
    asm volatile("cp.async.commit_group;" ::: "memory");
    load_stage(1, BKB);
    asm volatile("cp.async.commit_group;" ::: "memory");
    load_stage(2, 2 * BKB);
    asm volatile("cp.async.commit_group;" ::: "memory");

    const int lrow = lane & 15;         // ldmatrix row within 16
    const int lchk = lane >> 4;         // ldmatrix chunk select

    uint32_t afr[2][4][4];              // double-buffered A fragments
    uint32_t bfr[2][8][2];              // double-buffered B fragments

    // load fragments for one k32 step into buffer 'buf'
    auto load_frags = [&](int buf, uint32_t sa, uint32_t sb, int ks) {
        #pragma unroll
        for (int i = 0; i < 4; i++) {
            int row = wm * 64 + i * 16 + lrow;
            ldsm4(afr[buf][i], sa + swz(row, ks * 2 + lchk));
        }
        #pragma unroll
        for (int jj = 0; jj < 4; jj++) {
            uint32_t r[4];
            int row = wn * 64 + jj * 16 + lrow;
            ldsm4(r, sb + swz(row, ks * 2 + lchk));
            bfr[buf][jj*2][0]   = r[0]; bfr[buf][jj*2][1]   = r[2];
            bfr[buf][jj*2+1][0] = r[1]; bfr[buf][jj*2+1][1] = r[3];
        }
    };

    for (int it = 0; it < NIT; ++it) {
        asm volatile("cp.async.wait_group 2;" ::: "memory");
        __syncthreads();

        // issue next load (overwrites stage consumed last iter; sync above guards)
        int nt = it + 3;
        if (nt < NIT) load_stage(nt % NSTAGE, nt * BKB);
        asm volatile("cp.async.commit_group;" ::: "memory");

        const int st = it % NSTAGE;
        const uint32_t sa = sbase + st * STAGE_BYTES;
        const uint32_t sb = sa + A_BYTES;

        load_frags(0, sa, sb, 0);       // prologue: ks=0 fragments

        #pragma unroll
        for (int ks = 0; ks < 4; ks++) {    // four k32 steps per 128B stage
            const int cur = ks & 1;
            if (ks < 3) load_frags(cur ^ 1, sa, sb, ks + 1);   // prefetch next step
            #pragma unroll
            for (int i = 0; i < 4; i++)
                #pragma unroll
                for (int j = 0; j < 8; j++)
                    mma_s8(acc[i][j], afr[cur][i], bfr[cur][j]);
        }
    }

    // epilogue: direct int2 streaming stores (acc has no reuse until ln_out)
    #pragma unroll
    for (int i = 0; i < 4; i++) {
        #pragma unroll
        for (int j = 0; j < 8; j++) {
            int r0  = bm + wm * 64 + i * 16 + (lane >> 2);
            int col = bn + wn * 64 + j * 8 + (lane & 3) * 2;
            int2 v0; v0.x = acc[i][j][0]; v0.y = acc[i][j][1];
            int2 v1; v1.x = acc[i][j][2]; v1.y = acc[i][j][3];
            __stcs((int2*)(g_acc + (size_t)r0 * N_DIM + col), v0);
            __stcs((int2*)(g_acc + (size_t)(r0 + 8) * N_DIM + col), v1);
        }
    }
}

// ---------------------------------------------------------------------------
// Kernel 3: fused dequant (x_scale[t] * w_scale[o]) + output LayerNorm.
// ---------------------------------------------------------------------------
__global__ __launch_bounds__(256) void ln_out_kernel(const float* __restrict__ wscale,
                                                     float* __restrict__ out) {
    __shared__ float sh[18];
    const int row = blockIdx.x;
    const int t = threadIdx.x;
    const float s_t = g_xscale[row];

    const int4* ar = (const int4*)(g_acc + (size_t)row * N_DIM);
    const float4* ws = (const float4*)wscale;

    int4 a = __ldcs(&ar[t]);
    int4 b = __ldcs(&ar[t + 256]);
    float4 w0 = __ldg(&ws[t]);
    float4 w1 = __ldg(&ws[t + 256]);

    float v[8];
    v[0] = (float)a.x * s_t * w0.x;
    v[1] = (float)a.y * s_t * w0.y;
    v[2] = (float)a.z * s_t * w0.z;
    v[3] = (float)a.w * s_t * w0.w;
    v[4] = (float)b.x * s_t * w1.x;
    v[5] = (float)b.y * s_t * w1.y;
    v[6] = (float)b.z * s_t * w1.z;
    v[7] = (float)b.w * s_t * w1.w;

    float s = 0.f, ss = 0.f;
    #pragma unroll
    for (int i = 0; i < 8; i++) { s += v[i]; ss += v[i]*v[i]; }
    float2 tot = block_reduce_sum2(s, ss, sh);

    const float invn = 1.0f / (float)N_DIM;
    float mu  = tot.x * invn;
    float var = fmaxf(tot.y * invn - mu * mu, 0.f);
    float rstd = rsqrtf(var + 1e-5f);

    float4* dst = (float4*)(out + (size_t)row * N_DIM);
    float4 o0, o1;
    o0.x = (v[0]-mu)*rstd; o0.y = (v[1]-mu)*rstd;
    o0.z = (v[2]-mu)*rstd; o0.w = (v[3]-mu)*rstd;
    o1.x = (v[4]-mu)*rstd; o1.y = (v[5]-mu)*rstd;
    o1.z = (v[6]-mu)*rstd; o1.w = (v[7]-mu)*rstd;
    __stcs(&dst[t], o0);
    __stcs(&dst[t + 256], o1);
}

// ---------------------------------------------------------------------------
// Launch (single stream; GEMM split 888 + 136 CTAs = identical wave count)
// ---------------------------------------------------------------------------
extern "C" void kernel_launch(void* const* d_in, const int* in_sizes, int n_in,
                              void* d_out, int out_size) {
    const float* x  = (const float*)d_in[0];          // [4,4096,2048] f32
    const int*   wt = (const int*)d_in[1];            // [2048,2048] i32 ternary
    const float* ws = (const float*)d_in[2];          // [2048] f32
    float* out = (float*)d_out;                       // [4,4096,2048] f32

    cudaFuncSetAttribute(gemm_kernel, cudaFuncAttributeMaxDynamicSharedMemorySize, SMEM_DYN);

    pack_w_kernel<<<(N_DIM * K_DIM / 4 + 255) / 256, 256>>>(wt);
    ln_quant_kernel<<<M_TOK, 256>>>(x);

    dim3 grid1(N_DIM / BN, 111);   // 888 CTAs: rows 0..14207
    dim3 grid2(N_DIM / BN, 17);    // 136 CTAs: rows 14208..16383
    gemm_kernel<<<grid1, 256, SMEM_DYN>>>(0);
    gemm_kernel<<<grid2, 256, SMEM_DYN>>>(111 * BM);

    ln_out_kernel<<<M_TOK, 256>>>(ws, out);
}

// round 9
// speedup vs baseline: 1.0290x; 1.0290x over previous
#include <cuda_runtime.h>
#include <cuda_bf16.h>
#include <cstdint>

#define M_TOK 16384   // B*S tokens
#define K_DIM 2048    // DIN
#define N_DIM 2048    // DOUT

// ---------------------------------------------------------------------------
// Scratch (__device__ globals; no allocations allowed)
// ---------------------------------------------------------------------------
__device__ int8_t g_xq[(size_t)M_TOK * K_DIM];      // 32 MB quantized activations
__device__ float  g_xscale[M_TOK];                  // per-token scale
__device__ int8_t g_w[(size_t)N_DIM * K_DIM];       // 4 MB ternary weights as int8
__device__ int    g_acc[(size_t)M_TOK * N_DIM];     // 128 MB int32 GEMM output

// ---------------------------------------------------------------------------
// Block reductions (256 threads). Layouts sized for 8 warps.
// ---------------------------------------------------------------------------
__device__ __forceinline__ void block_reduce_sum4(float& a, float& b, float& c, float& d,
                                                  float* sh) {
    #pragma unroll
    for (int o = 16; o > 0; o >>= 1) {
        a += __shfl_xor_sync(0xFFFFFFFFu, a, o);
        b += __shfl_xor_sync(0xFFFFFFFFu, b, o);
        c += __shfl_xor_sync(0xFFFFFFFFu, c, o);
        d += __shfl_xor_sync(0xFFFFFFFFu, d, o);
    }
    int w = threadIdx.x >> 5, l = threadIdx.x & 31;
    if (l == 0) { sh[w] = a; sh[w+8] = b; sh[w+16] = c; sh[w+24] = d; }
    __syncthreads();
    if (threadIdx.x < 32) {
        float va = (l < 8) ? sh[l]      : 0.f;
        float vb = (l < 8) ? sh[l + 8]  : 0.f;
        float vc = (l < 8) ? sh[l + 16] : 0.f;
        float vd = (l < 8) ? sh[l + 24] : 0.f;
        #pragma unroll
        for (int o = 4; o > 0; o >>= 1) {
            va += __shfl_xor_sync(0xFFFFFFFFu, va, o);
            vb += __shfl_xor_sync(0xFFFFFFFFu, vb, o);
            vc += __shfl_xor_sync(0xFFFFFFFFu, vc, o);
            vd += __shfl_xor_sync(0xFFFFFFFFu, vd, o);
        }
        if (l == 0) { sh[32] = va; sh[33] = vb; sh[34] = vc; sh[35] = vd; }
    }
    __syncthreads();
    a = sh[32]; b = sh[33]; c = sh[34]; d = sh[35];
    __syncthreads();
}

__device__ __forceinline__ void block_reduce_max2(float& a, float& b, float* sh) {
    #pragma unroll
    for (int o = 16; o > 0; o >>= 1) {
        a = fmaxf(a, __shfl_xor_sync(0xFFFFFFFFu, a, o));
        b = fmaxf(b, __shfl_xor_sync(0xFFFFFFFFu, b, o));
    }
    int w = threadIdx.x >> 5, l = threadIdx.x & 31;
    if (l == 0) { sh[w] = a; sh[w + 8] = b; }
    __syncthreads();
    if (threadIdx.x < 32) {
        float ma = (l < 8) ? sh[l]     : -1e30f;
        float mb = (l < 8) ? sh[l + 8] : -1e30f;
        #pragma unroll
        for (int o = 4; o > 0; o >>= 1) {
            ma = fmaxf(ma, __shfl_xor_sync(0xFFFFFFFFu, ma, o));
            mb = fmaxf(mb, __shfl_xor_sync(0xFFFFFFFFu, mb, o));
        }
        if (l == 0) { sh[32] = ma; sh[33] = mb; }
    }
    __syncthreads();
    a = sh[32]; b = sh[33];
    __syncthreads();
}

// ---------------------------------------------------------------------------
// Kernel 1: fused input LayerNorm + per-token int8 absmax quantization.
// 2 token rows per block. Blocks [M_TOK/2 ..) repack the ternary weights.
// Per-row element->thread mapping identical to the 1-row version (FP order
// preserved bit-for-bit).
// ---------------------------------------------------------------------------
#define LNQ_BLOCKS (M_TOK / 2)                       // 8192
#define PACK_BLOCKS 2048                              // 2048*512 int4 = 4M elems
__global__ __launch_bounds__(256) void ln_quant_kernel(const float* __restrict__ x,
                                                       const int* __restrict__ wt) {
    const int t = threadIdx.x;

    if (blockIdx.x >= LNQ_BLOCKS) {
        // weight repack role: int32 ternary -> int8
        int base = (int)(blockIdx.x - LNQ_BLOCKS) * 512 + t * 2;
        #pragma unroll
        for (int l = 0; l < 2; l++) {
            int idx = base + l;
            int4 v = __ldcs(&((const int4*)wt)[idx]);
            char4 c;
            c.x = (char)v.x; c.y = (char)v.y; c.z = (char)v.z; c.w = (char)v.w;
            ((char4*)g_w)[idx] = c;
        }
        return;
    }

    __shared__ float sh[36];
    const int row0 = (int)blockIdx.x * 2;
    const int row1 = row0 + 1;
    const float4* xr0 = (const float4*)(x + (size_t)row0 * K_DIM);
    const float4* xr1 = (const float4*)(x + (size_t)row1 * K_DIM);

    float v0[8], v1[8];
    {
        float4 a = __ldcs(&xr0[t]);
        float4 b = __ldcs(&xr0[t + 256]);
        v0[0]=a.x; v0[1]=a.y; v0[2]=a.z; v0[3]=a.w;
        v0[4]=b.x; v0[5]=b.y; v0[6]=b.z; v0[7]=b.w;
        float4 c = __ldcs(&xr1[t]);
        float4 d = __ldcs(&xr1[t + 256]);
        v1[0]=c.x; v1[1]=c.y; v1[2]=c.z; v1[3]=c.w;
        v1[4]=d.x; v1[5]=d.y; v1[6]=d.z; v1[7]=d.w;
    }

    float s0 = 0.f, ss0 = 0.f, s1 = 0.f, ss1 = 0.f;
    #pragma unroll
    for (int i = 0; i < 8; i++) {
        s0 += v0[i]; ss0 += v0[i]*v0[i];
        s1 += v1[i]; ss1 += v1[i]*v1[i];
    }
    block_reduce_sum4(s0, ss0, s1, ss1, sh);

    const float invn = 1.0f / (float)K_DIM;
    float mu0  = s0 * invn;
    float var0 = fmaxf(ss0 * invn - mu0 * mu0, 0.f);
    float rstd0 = rsqrtf(var0 + 1e-5f);
    float mu1  = s1 * invn;
    float var1 = fmaxf(ss1 * invn - mu1 * mu1, 0.f);
    float rstd1 = rsqrtf(var1 + 1e-5f);

    float amax0 = 0.f, amax1 = 0.f;
    #pragma unroll
    for (int i = 0; i < 8; i++) {
        v0[i] = (v0[i] - mu0) * rstd0;
        amax0 = fmaxf(amax0, fabsf(v0[i]));
        v1[i] = (v1[i] - mu1) * rstd1;
        amax1 = fmaxf(amax1, fabsf(v1[i]));
    }
    block_reduce_max2(amax0, amax1, sh);
    amax0 = fmaxf(amax0, 1e-5f);
    amax1 = fmaxf(amax1, 1e-5f);
    float inv0 = 127.0f / amax0;
    float inv1 = 127.0f / amax1;

    char q0[8], q1[8];
    #pragma unroll
    for (int i = 0; i < 8; i++) {
        int a = (int)rintf(v0[i] * inv0);          // round-half-even
        q0[i] = (char)max(-127, min(127, a));
        int b = (int)rintf(v1[i] * inv1);
        q1[i] = (char)max(-127, min(127, b));
    }
    char4* d0 = (char4*)(g_xq + (size_t)row0 * K_DIM);
    char4* d1 = (char4*)(g_xq + (size_t)row1 * K_DIM);
    char4 c;
    c.x=q0[0]; c.y=q0[1]; c.z=q0[2]; c.w=q0[3]; d0[t]       = c;
    c.x=q0[4]; c.y=q0[5]; c.z=q0[6]; c.w=q0[7]; d0[t + 256] = c;
    c.x=q1[0]; c.y=q1[1]; c.z=q1[2]; c.w=q1[3]; d1[t]       = c;
    c.x=q1[4]; c.y=q1[5]; c.z=q1[6]; c.w=q1[7]; d1[t + 256] = c;
    if (t == 0) {
        g_xscale[row0] = amax0 * (1.0f / 127.0f);
        g_xscale[row1] = amax1 * (1.0f / 127.0f);
    }
}

// ---------------------------------------------------------------------------
// Kernel 2: int8 tensor-core GEMM via mma.sync.m16n8k32.
// CTA tile 128x256, K staged 128B, 8 warps (2x4), warp tile 64x64,
// 4-stage cp.async pipeline.  acc[m][n] = sum_k xq[m][k] * w[n][k]
// At the legacy-IMMA rate (~1024 MAC/cyc/SM) this mainloop is pipe-saturated.
// ---------------------------------------------------------------------------
#define BM  128
#define BN  256
#define BKB 128   // K-bytes per stage
#define NIT (K_DIM / BKB)   // 16
#define NSTAGE 4
#define A_BYTES (BM * BKB)                // 16 KB
#define B_BYTES (BN * BKB)                // 32 KB
#define STAGE_BYTES (A_BYTES + B_BYTES)   // 48 KB
#define SMEM_DYN (NSTAGE * STAGE_BYTES)   // 192 KB

__device__ __forceinline__ uint32_t smem_u32(const void* p) {
    uint32_t a;
    asm("{ .reg .u64 t; cvta.to.shared.u64 t, %1; cvt.u32.u64 %0, t; }" : "=r"(a) : "l"(p));
    return a;
}

// swizzled byte offset within a [rows x 128B] tile
__device__ __forceinline__ uint32_t swz(int row, int c) {
    return (uint32_t)(row * 128 + ((c ^ (row & 7)) << 4));
}

__device__ __forceinline__ void cp16(uint32_t saddr, const void* g) {
    asm volatile("cp.async.cg.shared.global [%0], [%1], 16;" :: "r"(saddr), "l"(g));
}

__device__ __forceinline__ void ldsm4(uint32_t* r, uint32_t addr) {
    asm volatile("ldmatrix.sync.aligned.m8n8.x4.shared.b16 {%0,%1,%2,%3}, [%4];"
                 : "=r"(r[0]), "=r"(r[1]), "=r"(r[2]), "=r"(r[3]) : "r"(addr));
}

__device__ __forceinline__ void mma_s8(int* c, const uint32_t* a, const uint32_t* b) {
    asm volatile(
        "mma.sync.aligned.m16n8k32.row.col.s32.s8.s8.s32 "
        "{%0,%1,%2,%3}, {%4,%5,%6,%7}, {%8,%9}, {%0,%1,%2,%3};"
        : "+r"(c[0]), "+r"(c[1]), "+r"(c[2]), "+r"(c[3])
        : "r"(a[0]), "r"(a[1]), "r"(a[2]), "r"(a[3]), "r"(b[0]), "r"(b[1]));
}

__global__ __launch_bounds__(256, 1) void gemm_kernel() {
    extern __shared__ uint8_t smem[];

    const int tid  = threadIdx.x;
    const int wid  = tid >> 5;
    const int lane = tid & 31;
    const int wm   = wid >> 2;          // 0..1 -> m offset wm*64
    const int wn   = wid & 3;           // 0..3 -> n offset wn*64
    const int bm   = (int)blockIdx.y * BM;
    const int bn   = (int)blockIdx.x * BN;
    const uint32_t sbase = smem_u32(smem);

    int acc[4][8][4];
    #pragma unroll
    for (int i = 0; i < 4; i++)
        #pragma unroll
        for (int j = 0; j < 8; j++)
            #pragma unroll
            for (int r = 0; r < 4; r++) acc[i][j][r] = 0;

    // cooperative load of one stage: A 1024 + B 2048 chunks of 16B = 12/thread
    auto load_stage = [&](int st, int k0) {
        uint32_t sa = sbase + st * STAGE_BYTES;
        uint32_t sb = sa + A_BYTES;
        #pragma unroll
        for (int i = 0; i < 12; i++) {
            int idx = tid + i * 256;        // 0..3071
            if (idx < 1024) {
                int row = idx >> 3, c = idx & 7;
                cp16(sa + swz(row, c), g_xq + (size_t)(bm + row) * K_DIM + k0 + c * 16);
            } else {
                int j = idx - 1024;
                int row = j >> 3, c = j & 7;
                cp16(sb + swz(row, c), g_w + (size_t)(bn + row) * K_DIM + k0 + c * 16);
            }
        }
    };

    // prologue: 3 stages in flight
    load_stage(0, 0);
    asm volatile("cp.async.commit_group;" ::: "memory");
    load_stage(1, BKB);
    asm volatile("cp.async.commit_group;" ::: "memory");
    load_stage(2, 2 * BKB);
    asm volatile("cp.async.commit_group;" ::: "memory");

    const int lrow = lane & 15;         // ldmatrix row within 16
    const int lchk = lane >> 4;         // ldmatrix chunk select

    for (int it = 0; it < NIT; ++it) {
        asm volatile("cp.async.wait_group 2;" ::: "memory");
        __syncthreads();

        // issue next load (overwrites stage consumed last iter; sync above guards)
        int nt = it + 3;
        if (nt < NIT) load_stage(nt % NSTAGE, nt * BKB);
        asm volatile("cp.async.commit_group;" ::: "memory");

        const int st = it % NSTAGE;
        const uint32_t sa = sbase + st * STAGE_BYTES;
        const uint32_t sb = sa + A_BYTES;

        #pragma unroll
        for (int ks = 0; ks < 4; ks++) {    // four k32 steps per 128B stage
            uint32_t a[4][4];
            #pragma unroll
            for (int i = 0; i < 4; i++) {
                int row = wm * 64 + i * 16 + lrow;
                ldsm4(a[i], sa + swz(row, ks * 2 + lchk));
            }
            uint32_t b[8][2];
            #pragma unroll
            for (int jj = 0; jj < 4; jj++) {
                uint32_t r[4];
                int row = wn * 64 + jj * 16 + lrow;
                ldsm4(r, sb + swz(row, ks * 2 + lchk));
                b[jj*2][0]   = r[0]; b[jj*2][1]   = r[2];
                b[jj*2+1][0] = r[1]; b[jj*2+1][1] = r[3];
            }
            #pragma unroll
            for (int i = 0; i < 4; i++)
                #pragma unroll
                for (int j = 0; j < 8; j++)
                    mma_s8(acc[i][j], a[i], b[j]);
        }
    }

    // epilogue: direct int2 streaming stores (acc has no reuse until ln_out)
    #pragma unroll
    for (int i = 0; i < 4; i++) {
        #pragma unroll
        for (int j = 0; j < 8; j++) {
            int r0  = bm + wm * 64 + i * 16 + (lane >> 2);
            int col = bn + wn * 64 + j * 8 + (lane & 3) * 2;
            int2 v0; v0.x = acc[i][j][0]; v0.y = acc[i][j][1];
            int2 v1; v1.x = acc[i][j][2]; v1.y = acc[i][j][3];
            __stcs((int2*)(g_acc + (size_t)r0 * N_DIM + col), v0);
            __stcs((int2*)(g_acc + (size_t)(r0 + 8) * N_DIM + col), v1);
        }
    }
}

// ---------------------------------------------------------------------------
// Kernel 3: fused dequant (x_scale[t] * w_scale[o]) + output LayerNorm.
// 2 token rows per block; per-row FP reduction order unchanged.
// ---------------------------------------------------------------------------
__global__ __launch_bounds__(256) void ln_out_kernel(const float* __restrict__ wscale,
                                                     float* __restrict__ out) {
    __shared__ float sh[36];
    const int row0 = (int)blockIdx.x * 2;
    const int row1 = row0 + 1;
    const int t = threadIdx.x;
    const float st0 = g_xscale[row0];
    const float st1 = g_xscale[row1];

    const int4* ar0 = (const int4*)(g_acc + (size_t)row0 * N_DIM);
    const int4* ar1 = (const int4*)(g_acc + (size_t)row1 * N_DIM);
    const float4* ws = (const float4*)wscale;

    int4 a0 = __ldcs(&ar0[t]);
    int4 b0 = __ldcs(&ar0[t + 256]);
    int4 a1 = __ldcs(&ar1[t]);
    int4 b1 = __ldcs(&ar1[t + 256]);
    float4 w0 = __ldg(&ws[t]);
    float4 w1 = __ldg(&ws[t + 256]);

    float v0[8], v1[8];
    v0[0] = (float)a0.x * st0 * w0.x;
    v0[1] = (float)a0.y * st0 * w0.y;
    v0[2] = (float)a0.z * st0 * w0.z;
    v0[3] = (float)a0.w * st0 * w0.w;
    v0[4] = (float)b0.x * st0 * w1.x;
    v0[5] = (float)b0.y * st0 * w1.y;
    v0[6] = (float)b0.z * st0 * w1.z;
    v0[7] = (float)b0.w * st0 * w1.w;
    v1[0] = (float)a1.x * st1 * w0.x;
    v1[1] = (float)a1.y * st1 * w0.y;
    v1[2] = (float)a1.z * st1 * w0.z;
    v1[3] = (float)a1.w * st1 * w0.w;
    v1[4] = (float)b1.x * st1 * w1.x;
    v1[5] = (float)b1.y * st1 * w1.y;
    v1[6] = (float)b1.z * st1 * w1.z;
    v1[7] = (float)b1.w * st1 * w1.w;

    float s0 = 0.f, ss0 = 0.f, s1 = 0.f, ss1 = 0.f;
    #pragma unroll
    for (int i = 0; i < 8; i++) {
        s0 += v0[i]; ss0 += v0[i]*v0[i];
        s1 += v1[i]; ss1 += v1[i]*v1[i];
    }
    block_reduce_sum4(s0, ss0, s1, ss1, sh);

    const float invn = 1.0f / (float)N_DIM;
    float mu0  = s0 * invn;
    float var0 = fmaxf(ss0 * invn - mu0 * mu0, 0.f);
    float rstd0 = rsqrtf(var0 + 1e-5f);
    float mu1  = s1 * invn;
    float var1 = fmaxf(ss1 * invn - mu1 * mu1, 0.f);
    float rstd1 = rsqrtf(var1 + 1e-5f);

    float4* d0 = (float4*)(out + (size_t)row0 * N_DIM);
    float4* d1 = (float4*)(out + (size_t)row1 * N_DIM);
    float4 o;
    o.x = (v0[0]-mu0)*rstd0; o.y = (v0[1]-mu0)*rstd0;
    o.z = (v0[2]-mu0)*rstd0; o.w = (v0[3]-mu0)*rstd0;
    __stcs(&d0[t], o);
    o.x = (v0[4]-mu0)*rstd0; o.y = (v0[5]-mu0)*rstd0;
    o.z = (v0[6]-mu0)*rstd0; o.w = (v0[7]-mu0)*rstd0;
    __stcs(&d0[t + 256], o);
    o.x = (v1[0]-mu1)*rstd1; o.y = (v1[1]-mu1)*rstd1;
    o.z = (v1[2]-mu1)*rstd1; o.w = (v1[3]-mu1)*rstd1;
    __stcs(&d1[t], o);
    o.x = (v1[4]-mu1)*rstd1; o.y = (v1[5]-mu1)*rstd1;
    o.z = (v1[6]-mu1)*rstd1; o.w = (v1[7]-mu1)*rstd1;
    __stcs(&d1[t + 256], o);
}

// ---------------------------------------------------------------------------
// Launch (3 kernels: ln_quant+pack fused, gemm, ln_out)
// ---------------------------------------------------------------------------
extern "C" void kernel_launch(void* const* d_in, const int* in_sizes, int n_in,
                              void* d_out, int out_size) {
    const float* x  = (const float*)d_in[0];          // [4,4096,2048] f32
    const int*   wt = (const int*)d_in[1];            // [2048,2048] i32 ternary
    const float* ws = (const float*)d_in[2];          // [2048] f32
    float* out = (float*)d_out;                       // [4,4096,2048] f32

    cudaFuncSetAttribute(gemm_kernel, cudaFuncAttributeMaxDynamicSharedMemorySize, SMEM_DYN);

    ln_quant_kernel<<<LNQ_BLOCKS + PACK_BLOCKS, 256>>>(x, wt);
    dim3 grid(N_DIM / BN, M_TOK / BM);                // (8, 128) = 1024 CTAs
    gemm_kernel<<<grid, 256, SMEM_DYN>>>();
    ln_out_kernel<<<M_TOK / 2, 256>>>(ws, out);
}